// round 10
// baseline (speedup 1.0000x reference)
#include <cuda_runtime.h>
#include <cuda_fp16.h>
#include <math.h>
#include <stdint.h>

#define DDIM 16
#define KCOMP 32
#define NQSTEPS 10             // quad k16 steps (40 chunks)
#define NSTEPS 11              // + 1 linear step
#define BST 104                // B words per component (88 used; 104%32=8 -> CF)
#define TPB 128
#define XBUF (TPB * DDIM)      // floats per staging buffer
#define ESETUP 2               // tiles of head-start given to non-setup CTAs
#define FXSCALE 16777216.0     // 2^24 fixed-point scale
#define LOG_2PI 1.8378770664093453f

// chunk tables: chunk c = 4*s + (kk>>2); quad chunks c=0..39, linear 40..43
#define CHUNK_TABLES \
    const int CI[40] = { 0,0,0,0, 1,1,1,1, 2,2,2,2, 3,3,3,3, \
                         4,4,4,5, 5,5,6,6, 6,7,7,7, \
                         8,8,9,9, 10,10,11,11, 12,13,14,15 }; \
    const int CO[40] = { 0,1,2,3, 0,1,2,3, 0,1,2,3, 0,1,2,3, \
                         1,2,3,1, 2,3,1,2, 3,1,2,3, \
                         2,3,2,3, 2,3,2,3, 3,3,3,3 };

__device__ uint32_t g_B[KCOMP * BST];   // fp16x2-packed weights
__device__ float g_const[KCOMP];
__device__ unsigned long long g_sum;    // fixed-point total (self-resetting)
__device__ unsigned int g_done;         // setup completion count (self-resetting)
__device__ unsigned int g_ticket;       // last-block ticket (self-resetting)

__device__ __forceinline__ uint32_t smem_u32(const void* p) {
    uint32_t a;
    asm("{ .reg .u64 t; cvta.to.shared.u64 t, %1; cvt.u32.u64 %0, t; }"
        : "=r"(a) : "l"(p));
    return a;
}
__device__ __forceinline__ uint32_t pack_h2(float lo, float hi) {
    uint32_t r;
    asm("cvt.rn.f16x2.f32 %0, %1, %2;" : "=r"(r) : "f"(hi), "f"(lo));
    return r;
}
__device__ __forceinline__ void ldsv2(uint32_t& a, uint32_t& b, uint32_t addr) {
    asm volatile("ld.shared.v2.b32 {%0, %1}, [%2];" : "=r"(a), "=r"(b) : "r"(addr));
}
__device__ __forceinline__ void mma_f16(float* c,
                                        uint32_t a0, uint32_t a1, uint32_t a2, uint32_t a3,
                                        uint32_t b0, uint32_t b1) {
    asm volatile(
        "mma.sync.aligned.m16n8k16.row.col.f32.f16.f16.f32 "
        "{%0,%1,%2,%3}, {%4,%5,%6,%7}, {%8,%9}, {%0,%1,%2,%3};"
        : "+f"(c[0]), "+f"(c[1]), "+f"(c[2]), "+f"(c[3])
        : "r"(a0), "r"(a1), "r"(a2), "r"(a3), "r"(b0), "r"(b1));
}
__device__ __forceinline__ void cp16(uint32_t dst, const void* src) {
    asm volatile("cp.async.ca.shared.global [%0], [%1], 16;"
                 :: "r"(dst), "l"(src) : "memory");
}

// ---------------------------------------------------------------------------
// Warp-level setup for component k (32 lanes). Identical math/packing to the
// proven standalone version: cov=AA^T; chol w/ rsqrt; M=L^{-1}; P=M^T M;
// b=Pmu; fp16x2 pack into g_B; g_const[k].
// ---------------------------------------------------------------------------
struct SetupSmem {
    float A[DDIM][DDIM];
    float C[DDIM][DDIM + 1];
    float Mi[DDIM][DDIM + 1];
    float P[DDIM][DDIM + 1];
    float bv[DDIM];
    float rdg[DDIM];
    float lgs[DDIM];
};

__device__ void warp_setup(int k, int t, SetupSmem* S,
                           const float* __restrict__ means,
                           const float* __restrict__ cov_parts,
                           const float* __restrict__ logw)
{
    #pragma unroll
    for (int e = 0; e < 8; e++) {
        int idx = t * 8 + e;
        S->A[idx >> 4][idx & 15] = cov_parts[k * DDIM * DDIM + idx];
    }
    __syncwarp();

    #pragma unroll
    for (int e = 0; e < 8; e++) {
        int idx = t * 8 + e;
        int i = idx >> 4, l = idx & 15;
        float s = 0.f;
        #pragma unroll
        for (int j = 0; j < DDIM; j++) s += S->A[i][j] * S->A[l][j];
        S->C[i][l] = s;
    }
    __syncwarp();

    for (int j = 0; j < DDIM; j++) {
        if (t == j) {
            float d = S->C[j][j];
            float rs = rsqrtf(d);
            S->rdg[j] = rs;
            S->C[j][j] = d * rs;
        }
        __syncwarp();
        if (t > j && t < DDIM) S->C[t][j] *= S->rdg[j];
        __syncwarp();
        if (t > j && t < DDIM) {
            for (int l = j + 1; l <= t; l++) S->C[t][l] -= S->C[t][j] * S->C[l][j];
        }
        __syncwarp();
    }

    if (t < DDIM) {
        int c = t;
        for (int i = 0; i < c; i++) S->Mi[i][c] = 0.f;
        S->Mi[c][c] = S->rdg[c];
        for (int i = c + 1; i < DDIM; i++) {
            float s = 0.f;
            for (int j = c; j < i; j++) s += S->C[i][j] * S->Mi[j][c];
            S->Mi[i][c] = -s * S->rdg[i];
        }
        S->lgs[t] = __logf(S->C[t][t]);
    }
    __syncwarp();

    #pragma unroll
    for (int e = 0; e < 8; e++) {
        int idx = t * 8 + e;
        int i = idx >> 4, j = idx & 15;
        float s = 0.f;
        #pragma unroll
        for (int l = 0; l < DDIM; l++) s += S->Mi[l][i] * S->Mi[l][j];
        S->P[i][j] = s;
    }
    __syncwarp();

    if (t < DDIM) {
        float s = 0.f;
        for (int j = 0; j < DDIM; j++) s += S->P[t][j] * means[k * DDIM + j];
        S->bv[t] = s;
    }
    __syncwarp();

    if (t == 0) {
        float muPmu = 0.f, logdet = 0.f;
        #pragma unroll
        for (int i = 0; i < DDIM; i++) {
            muPmu += S->bv[i] * means[k * DDIM + i];
            logdet += S->lgs[i];
        }
        float lw = logw[k];
        g_const[k] = -0.5f * muPmu - logdet - 0.5f * (float)DDIM * LOG_2PI + lw * lw;
    }
    __syncwarp();

    for (int w = t; w < NSTEPS * 8; w += 32) {
        CHUNK_TABLES
        const int s  = w >> 3;
        const int r  = w & 7;
        const int wp = r >> 1;
        const int hh = r & 1;
        float cf[2];
        #pragma unroll
        for (int e = 0; e < 2; e++) {
            const int kk = hh * 8 + 2 * wp + e;
            float coeff = 0.f;
            if (s < NQSTEPS) {
                const int c = 4 * s + (kk >> 2);
                const int i = CI[c];
                const int j = CO[c] * 4 + (kk & 3);
                if (j > i)       coeff = -S->P[i][j];
                else if (j == i) coeff = -0.5f * S->P[i][i];
            } else {
                coeff = S->bv[kk];
            }
            cf[e] = coeff;
        }
        g_B[k * BST + s * 8 + 2 * wp + hh] = pack_h2(cf[0], cf[1]);
    }
}

// ---------------------------------------------------------------------------
// Fused kernel: in-kernel setup (first 32 CTAs) + spin sync + persistent MMA
// main loop + fixed-point grid reduction with last-block finalize.
// ---------------------------------------------------------------------------
__global__ void __launch_bounds__(TPB, 3)
mog_fused(const float* __restrict__ data,
          const float* __restrict__ means,
          const float* __restrict__ cov_parts,
          const float* __restrict__ logw,
          float* __restrict__ out,
          int N, int nIt, int grid)
{
    __shared__ uint32_t Bsh[KCOMP * BST];
    __shared__ float sx[2][XBUF];
    __shared__ float s_red[TPB];
    __shared__ SetupSmem ss;

    const int tid  = threadIdx.x;
    const int lane = tid & 31;
    const int warp = tid >> 5;
    const int gr   = lane >> 2;     // 0..7
    const int tg   = lane & 3;      // 0..3
    const bool p2  = (tg < 2);
    const bool podd = (tg & 1);
    const int bid  = blockIdx.x;

    // ---- contiguous tile partition (setup CTAs get ESETUP fewer tiles) ----
    int t0, t1;
    if (grid >= KCOMP) {
        int total = nIt + KCOMP * ESETUP;
        int q = (total + grid - 1) / grid;
        int qs = q - ESETUP; if (qs < 0) qs = 0;
        if (bid < KCOMP) { t0 = bid * qs;              t1 = t0 + qs; }
        else             { t0 = KCOMP * qs + (bid - KCOMP) * q; t1 = t0 + q; }
    } else {
        int q = (nIt + grid - 1) / grid;
        t0 = bid * q; t1 = t0 + q;
    }
    if (t1 > nIt) t1 = nIt;
    if (t0 > t1)  t0 = t1;

    const uint32_t sxB   = smem_u32(sx);
    const uint32_t myDst = sxB + (uint32_t)tid * 64u;

    // ---- prologue: stage first tile (overlaps setup/spin) ----
    {
        int st = t0 < nIt ? t0 : nIt - 1;
        int idxp = st * TPB + tid;
        int pt = idxp < N ? idxp : N - 1;
        const char* g = (const char*)(data + (size_t)pt * DDIM);
        #pragma unroll
        for (int v = 0; v < 4; v++) cp16(myDst + 16u * v, g + 16 * v);
        asm volatile("cp.async.commit_group;" ::: "memory");
    }

    // ---- in-kernel setup: warp 0 of designated CTAs ----
    if (warp == 0) {
        for (int k = bid; k < KCOMP; k += grid) {
            warp_setup(k, lane, &ss, means, cov_parts, logw);
            __threadfence();
            __syncwarp();
            if (lane == 0) atomicAdd(&g_done, 1u);
        }
    }

    // ---- spin until all components published ----
    if (tid == 0) {
        while (*((volatile unsigned int*)&g_done) < KCOMP) { }
        __threadfence();
    }
    __syncthreads();

    // ---- load B image + consts ----
    for (int i = tid; i < KCOMP * BST; i += TPB) Bsh[i] = g_B[i];
    float kc[4][2];
    #pragma unroll
    for (int n = 0; n < 4; n++) {
        kc[n][0] = g_const[n * 8 + 2 * tg];
        kc[n][1] = g_const[n * 8 + 2 * tg + 1];
    }
    __syncthreads();

    const uint32_t bBase = smem_u32(Bsh);
    const uint32_t bRd = bBase + ((uint32_t)gr * BST + 2u * (uint32_t)tg) * 4u;

    float acc = 0.f;
    int buf = 0;

    for (int tile = t0; tile < t1; tile++) {
        // ---- stage NEXT tile into other buffer ----
        {
            int nxt = tile + 1;
            if (nxt < t1) {
                int idxp = nxt * TPB + tid;
                int pt = idxp < N ? idxp : N - 1;
                const char* g = (const char*)(data + (size_t)pt * DDIM);
                uint32_t d = myDst + (uint32_t)(buf ^ 1) * (XBUF * 4u);
                #pragma unroll
                for (int v = 0; v < 4; v++) cp16(d + 16u * v, g + 16 * v);
            }
            asm volatile("cp.async.commit_group;" ::: "memory");
        }
        asm volatile("cp.async.wait_group 1;" ::: "memory");
        __syncwarp();

        const int base = tile * TPB + warp * 32;

        // ---- read 4 points from staging (rows gr, gr+8, gr+16, gr+24) ----
        float x[4][DDIM];
        #pragma unroll
        for (int p = 0; p < 4; p++) {
            const float4* s =
                (const float4*)&sx[buf][(warp * 32 + gr + 8 * p) * DDIM];
            #pragma unroll
            for (int v4 = 0; v4 < 4; v4++) {
                float4 f = s[v4];
                x[p][v4 * 4 + 0] = f.x; x[p][v4 * 4 + 1] = f.y;
                x[p][v4 * 4 + 2] = f.z; x[p][v4 * 4 + 3] = f.w;
            }
        }
        __syncwarp();
        buf ^= 1;

        // ---- per-thread j-pair selection ----
        float xjl[4][4], xjh[4][4];
        #pragma unroll
        for (int p = 0; p < 4; p++) {
            #pragma unroll
            for (int m = 0; m < 4; m++) {
                xjl[p][m] = podd ? x[p][4 * m + 2] : x[p][4 * m];
                xjh[p][m] = podd ? x[p][4 * m + 3] : x[p][4 * m + 1];
            }
        }

        float c[2][4][4];
        #pragma unroll
        for (int t2 = 0; t2 < 2; t2++)
            #pragma unroll
            for (int n = 0; n < 4; n++)
                #pragma unroll
                for (int q = 0; q < 4; q++) c[t2][n][q] = 0.f;

        // ---- 10 quad k16-steps + 1 linear step ----
        CHUNK_TABLES
        #pragma unroll
        for (int s = 0; s < NQSTEPS; s++) {
            uint32_t a[2][4];
            #pragma unroll
            for (int t2 = 0; t2 < 2; t2++) {
                #pragma unroll
                for (int pp = 0; pp < 2; pp++) {
                    const int p = t2 * 2 + pp;
                    float xi0 = p2 ? x[p][CI[4 * s]]     : x[p][CI[4 * s + 1]];
                    float l0  = p2 ? xjl[p][CO[4 * s]]   : xjl[p][CO[4 * s + 1]];
                    float h0  = p2 ? xjh[p][CO[4 * s]]   : xjh[p][CO[4 * s + 1]];
                    float xi1 = p2 ? x[p][CI[4 * s + 2]] : x[p][CI[4 * s + 3]];
                    float l1  = p2 ? xjl[p][CO[4 * s + 2]] : xjl[p][CO[4 * s + 3]];
                    float h1  = p2 ? xjh[p][CO[4 * s + 2]] : xjh[p][CO[4 * s + 3]];
                    a[t2][pp]     = pack_h2(xi0 * l0, xi0 * h0);
                    a[t2][pp + 2] = pack_h2(xi1 * l1, xi1 * h1);
                }
            }
            #pragma unroll
            for (int n = 0; n < 4; n++) {
                uint32_t b0, b1;
                ldsv2(b0, b1, bRd + ((uint32_t)(n * 8) * BST + (uint32_t)s * 8u) * 4u);
                mma_f16(c[0][n], a[0][0], a[0][1], a[0][2], a[0][3], b0, b1);
                mma_f16(c[1][n], a[1][0], a[1][1], a[1][2], a[1][3], b0, b1);
            }
        }
        {   // linear step s = 10
            uint32_t a[2][4];
            #pragma unroll
            for (int t2 = 0; t2 < 2; t2++) {
                #pragma unroll
                for (int pp = 0; pp < 2; pp++) {
                    const int p = t2 * 2 + pp;
                    float l0 = p2 ? xjl[p][0] : xjl[p][1];
                    float h0 = p2 ? xjh[p][0] : xjh[p][1];
                    float l1 = p2 ? xjl[p][2] : xjl[p][3];
                    float h1 = p2 ? xjh[p][2] : xjh[p][3];
                    a[t2][pp]     = pack_h2(l0, h0);
                    a[t2][pp + 2] = pack_h2(l1, h1);
                }
            }
            #pragma unroll
            for (int n = 0; n < 4; n++) {
                uint32_t b0, b1;
                ldsv2(b0, b1, bRd + ((uint32_t)(n * 8) * BST + 80u) * 4u);
                mma_f16(c[0][n], a[0][0], a[0][1], a[0][2], a[0][3], b0, b1);
                mma_f16(c[1][n], a[1][0], a[1][1], a[1][2], a[1][3], b0, b1);
            }
        }

        // ---- epilogue: add per-component const, exp, logsumexp ----
        #pragma unroll
        for (int t2 = 0; t2 < 2; t2++) {
            float S0 = 0.f, S1 = 0.f;
            #pragma unroll
            for (int n = 0; n < 4; n++) {
                S0 += __expf(c[t2][n][0] + kc[n][0]) + __expf(c[t2][n][1] + kc[n][1]);
                S1 += __expf(c[t2][n][2] + kc[n][0]) + __expf(c[t2][n][3] + kc[n][1]);
            }
            S0 += __shfl_xor_sync(0xffffffffu, S0, 1);
            S0 += __shfl_xor_sync(0xffffffffu, S0, 2);
            S1 += __shfl_xor_sync(0xffffffffu, S1, 1);
            S1 += __shfl_xor_sync(0xffffffffu, S1, 2);
            if (tg == 0) {
                int r0 = base + t2 * 16 + gr;
                if (r0 < N)     acc += __logf(S0);
                if (r0 + 8 < N) acc += __logf(S1);
            }
        }
    }

    // ---- block reduction (same order as before) ----
    s_red[tid] = acc;
    __syncthreads();
    for (int s = TPB / 2; s > 0; s >>= 1) {
        if (tid < s) s_red[tid] += s_red[tid + s];
        __syncthreads();
    }

    // ---- fixed-point grid reduction + last-block finalize (deterministic) ----
    if (tid == 0) {
        long long fx = llrint((double)s_red[0] * FXSCALE);
        atomicAdd(&g_sum, (unsigned long long)fx);
        __threadfence();
        unsigned int tk = atomicAdd(&g_ticket, 1u);
        if (tk == (unsigned int)(grid - 1)) {
            long long tot = (long long)g_sum;
            out[0] = (float)(((double)tot / FXSCALE) / (double)N);
            g_sum = 0ull;
            g_done = 0u;
            g_ticket = 0u;
            __threadfence();
        }
    }
}

// ---------------------------------------------------------------------------
extern "C" void kernel_launch(void* const* d_in, const int* in_sizes, int n_in,
                              void* d_out, int out_size)
{
    const float* data      = (const float*)d_in[0];
    const float* means     = (const float*)d_in[1];
    const float* cov_parts = (const float*)d_in[2];
    const float* logw      = (const float*)d_in[3];
    float* out = (float*)d_out;

    const int N = in_sizes[0] / DDIM;

    int sm = 148;
    cudaDeviceGetAttribute(&sm, cudaDevAttrMultiProcessorCount, 0);
    if (sm > 680) sm = 680;

    const int nIt = (N + TPB - 1) / TPB;
    int grid = sm * 3;                 // all CTAs co-resident (3/SM enforced)
    if (grid > nIt) grid = nIt;

    mog_fused<<<grid, TPB>>>(data, means, cov_parts, logw, out, N, nIt, grid);
}

// round 11
// speedup vs baseline: 1.0301x; 1.0301x over previous
#include <cuda_runtime.h>
#include <cuda_fp16.h>
#include <math.h>
#include <stdint.h>

#define DDIM 16
#define KCOMP 32
#define NQSTEPS 10             // quad k16 steps (40 chunks)
#define NSTEPS 11              // + 1 linear step
#define BST 104                // B words per component (88 used; 104%32=8 -> CF)
#define TPB 128
#define XBUF (TPB * DDIM)      // floats per staging buffer
#define LOG_2PI 1.8378770664093453f

// chunk tables: chunk c = 4*s + (kk>>2); quad chunks c=0..39, linear 40..43
#define CHUNK_TABLES \
    const int CI[40] = { 0,0,0,0, 1,1,1,1, 2,2,2,2, 3,3,3,3, \
                         4,4,4,5, 5,5,6,6, 6,7,7,7, \
                         8,8,9,9, 10,10,11,11, 12,13,14,15 }; \
    const int CO[40] = { 0,1,2,3, 0,1,2,3, 0,1,2,3, 0,1,2,3, \
                         1,2,3,1, 2,3,1,2, 3,1,2,3, \
                         2,3,2,3, 2,3,2,3, 3,3,3,3 };

__device__ uint32_t g_B[KCOMP * BST];   // fp16x2-packed weights
__device__ float g_const[KCOMP];
__device__ float g_partial[2048];

__device__ __forceinline__ uint32_t smem_u32(const void* p) {
    uint32_t a;
    asm("{ .reg .u64 t; cvta.to.shared.u64 t, %1; cvt.u32.u64 %0, t; }"
        : "=r"(a) : "l"(p));
    return a;
}
__device__ __forceinline__ uint32_t pack_h2(float lo, float hi) {
    uint32_t r;
    asm("cvt.rn.f16x2.f32 %0, %1, %2;" : "=r"(r) : "f"(hi), "f"(lo));
    return r;
}
__device__ __forceinline__ void ldsv2(uint32_t& a, uint32_t& b, uint32_t addr) {
    asm volatile("ld.shared.v2.b32 {%0, %1}, [%2];" : "=r"(a), "=r"(b) : "r"(addr));
}
__device__ __forceinline__ void mma_f16(float* c,
                                        uint32_t a0, uint32_t a1, uint32_t a2, uint32_t a3,
                                        uint32_t b0, uint32_t b1) {
    asm volatile(
        "mma.sync.aligned.m16n8k16.row.col.f32.f16.f16.f32 "
        "{%0,%1,%2,%3}, {%4,%5,%6,%7}, {%8,%9}, {%0,%1,%2,%3};"
        : "+f"(c[0]), "+f"(c[1]), "+f"(c[2]), "+f"(c[3])
        : "r"(a0), "r"(a1), "r"(a2), "r"(a3), "r"(b0), "r"(b1));
}
__device__ __forceinline__ void cp16(uint32_t dst, const void* src) {
    asm volatile("cp.async.ca.shared.global [%0], [%1], 16;"
                 :: "r"(dst), "l"(src) : "memory");
}
__device__ __forceinline__ __half2 dup_half(__half2 v, int hi) {
    return hi ? __high2half2(v) : __low2half2(v);
}

// ---------------------------------------------------------------------------
// Setup: ONE WARP per component (32 blocks x 32 threads). Warp-synchronous.
// cov=AA^T; chol w/ rsqrt; M=L^{-1}; P=M^T M; b=Pmu; fp16x2 pack of g_B.
// ---------------------------------------------------------------------------
__global__ void __launch_bounds__(32, 16)
mog_setup(const float* __restrict__ means,
          const float* __restrict__ cov_parts,
          const float* __restrict__ logw)
{
    const int k = blockIdx.x;
    const int t = threadIdx.x;      // 0..31

    __shared__ float A[DDIM][DDIM];
    __shared__ float C[DDIM][DDIM + 1];
    __shared__ float Mi[DDIM][DDIM + 1];
    __shared__ float P[DDIM][DDIM + 1];
    __shared__ float bv[DDIM];
    __shared__ float rdg[DDIM];
    __shared__ float lgs[DDIM];

    #pragma unroll
    for (int e = 0; e < 8; e++) {
        int idx = t * 8 + e;
        A[idx >> 4][idx & 15] = cov_parts[k * DDIM * DDIM + idx];
    }
    __syncwarp();

    #pragma unroll
    for (int e = 0; e < 8; e++) {
        int idx = t * 8 + e;
        int i = idx >> 4, l = idx & 15;
        float s = 0.f;
        #pragma unroll
        for (int j = 0; j < DDIM; j++) s += A[i][j] * A[l][j];
        C[i][l] = s;
    }
    __syncwarp();

    for (int j = 0; j < DDIM; j++) {
        if (t == j) {
            float d = C[j][j];
            float rs = rsqrtf(d);
            rdg[j] = rs;
            C[j][j] = d * rs;          // = sqrt(d)
        }
        __syncwarp();
        if (t > j && t < DDIM) C[t][j] *= rdg[j];
        __syncwarp();
        if (t > j && t < DDIM) {
            for (int l = j + 1; l <= t; l++) C[t][l] -= C[t][j] * C[l][j];
        }
        __syncwarp();
    }

    if (t < DDIM) {                    // M = L^{-1}, column t
        int c = t;
        for (int i = 0; i < c; i++) Mi[i][c] = 0.f;
        Mi[c][c] = rdg[c];
        for (int i = c + 1; i < DDIM; i++) {
            float s = 0.f;
            for (int j = c; j < i; j++) s += C[i][j] * Mi[j][c];
            Mi[i][c] = -s * rdg[i];
        }
        lgs[t] = __logf(C[t][t]);
    }
    __syncwarp();

    #pragma unroll
    for (int e = 0; e < 8; e++) {      // P = M^T M
        int idx = t * 8 + e;
        int i = idx >> 4, j = idx & 15;
        float s = 0.f;
        #pragma unroll
        for (int l = 0; l < DDIM; l++) s += Mi[l][i] * Mi[l][j];
        P[i][j] = s;
    }
    __syncwarp();

    if (t < DDIM) {                    // b = P mu
        float s = 0.f;
        for (int j = 0; j < DDIM; j++) s += P[t][j] * means[k * DDIM + j];
        bv[t] = s;
    }
    __syncwarp();

    if (t == 0) {
        float muPmu = 0.f, logdet = 0.f;
        #pragma unroll
        for (int i = 0; i < DDIM; i++) {
            muPmu += bv[i] * means[k * DDIM + i];
            logdet += lgs[i];
        }
        float lw = logw[k];
        g_const[k] = -0.5f * muPmu - logdet - 0.5f * (float)DDIM * LOG_2PI + lw * lw;
    }
    __syncwarp();

    for (int w = t; w < NSTEPS * 8; w += 32) {
        CHUNK_TABLES
        const int s  = w >> 3;
        const int r  = w & 7;
        const int wp = r >> 1;
        const int hh = r & 1;
        float cf[2];
        #pragma unroll
        for (int e = 0; e < 2; e++) {
            const int kk = hh * 8 + 2 * wp + e;
            float coeff = 0.f;
            if (s < NQSTEPS) {
                const int c = 4 * s + (kk >> 2);
                const int i = CI[c];
                const int j = CO[c] * 4 + (kk & 3);
                if (j > i)       coeff = -P[i][j];
                else if (j == i) coeff = -0.5f * P[i][i];
            } else {
                coeff = bv[kk];
            }
            cf[e] = coeff;
        }
        g_B[k * BST + s * 8 + 2 * wp + hh] = pack_h2(cf[0], cf[1]);
    }
}

// ---------------------------------------------------------------------------
// Main: persistent CTAs, 128 threads = 4 warps, 4 CTAs/SM (reg-slim half2
// path). Warp owns 32 points/iter. Points held as half2; A-fragments =
// HMUL2(dup(x_i), xq) -- short chains, fewer regs. 11 k16 steps, 88 HMMA.
// ---------------------------------------------------------------------------
__global__ void __launch_bounds__(TPB, 4)
mog_main(const float* __restrict__ data, int N, int nIt, int grid)
{
    __shared__ uint32_t Bsh[KCOMP * BST];
    __shared__ float sx[2][XBUF];
    __shared__ float s_red[TPB];

    const int tid  = threadIdx.x;
    const int lane = tid & 31;
    const int warp = tid >> 5;
    const int gr   = lane >> 2;     // 0..7
    const int tg   = lane & 3;      // 0..3
    const bool p2  = (tg < 2);
    const int podd = (tg & 1);

    for (int i = tid; i < KCOMP * BST; i += TPB) Bsh[i] = g_B[i];

    float kc[4][2];
    #pragma unroll
    for (int n = 0; n < 4; n++) {
        kc[n][0] = g_const[n * 8 + 2 * tg];
        kc[n][1] = g_const[n * 8 + 2 * tg + 1];
    }
    __syncthreads();

    const uint32_t bBase = smem_u32(Bsh);
    const uint32_t bRd = bBase + ((uint32_t)gr * BST + 2u * (uint32_t)tg) * 4u;
    const uint32_t sxB  = smem_u32(sx);
    const uint32_t myDst = sxB + (uint32_t)tid * 64u;            // producer slot

    float acc = 0.f;
    int buf = 0;

    // prologue: stage first tile
    {
        int idxp = blockIdx.x * TPB + tid;
        int pt = idxp < N ? idxp : N - 1;
        const char* g = (const char*)(data + (size_t)pt * DDIM);
        #pragma unroll
        for (int v = 0; v < 4; v++) cp16(myDst + 16u * v, g + 16 * v);
        asm volatile("cp.async.commit_group;" ::: "memory");
    }

    for (int tile = blockIdx.x; tile < nIt; tile += grid) {
        // ---- stage NEXT tile into other buffer ----
        {
            int nxt = tile + grid;
            if (nxt < nIt) {
                int idxp = nxt * TPB + tid;
                int pt = idxp < N ? idxp : N - 1;
                const char* g = (const char*)(data + (size_t)pt * DDIM);
                uint32_t d = myDst + (uint32_t)(buf ^ 1) * (XBUF * 4u);
                #pragma unroll
                for (int v = 0; v < 4; v++) cp16(d + 16u * v, g + 16 * v);
            }
            asm volatile("cp.async.commit_group;" ::: "memory");
        }
        asm volatile("cp.async.wait_group 1;" ::: "memory");
        __syncwarp();

        const int base = tile * TPB + warp * 32;

        // ---- read 4 points, convert to half2 pairs xh[p][i] = {x2i, x2i+1} ----
        __half2 xh[4][8];
        #pragma unroll
        for (int p = 0; p < 4; p++) {
            const float4* s =
                (const float4*)&sx[buf][(warp * 32 + gr + 8 * p) * DDIM];
            #pragma unroll
            for (int v4 = 0; v4 < 4; v4++) {
                float4 f = s[v4];
                xh[p][2 * v4]     = __floats2half2_rn(f.x, f.y);
                xh[p][2 * v4 + 1] = __floats2half2_rn(f.z, f.w);
            }
        }
        __syncwarp();
        buf ^= 1;

        // ---- per-thread j-pair: xq[p][m] = {x[4m+2podd], x[4m+2podd+1]} ----
        __half2 xq[4][4];
        #pragma unroll
        for (int p = 0; p < 4; p++) {
            #pragma unroll
            for (int m = 0; m < 4; m++) {
                xq[p][m] = podd ? xh[p][2 * m + 1] : xh[p][2 * m];
            }
        }

        float c[2][4][4];
        #pragma unroll
        for (int t2 = 0; t2 < 2; t2++)
            #pragma unroll
            for (int n = 0; n < 4; n++)
                #pragma unroll
                for (int q = 0; q < 4; q++) c[t2][n][q] = 0.f;

        // ---- 10 quad k16-steps + 1 linear step ----
        CHUNK_TABLES
        #pragma unroll
        for (int s = 0; s < NQSTEPS; s++) {
            uint32_t a[2][4];
            #pragma unroll
            for (int h = 0; h < 2; h++) {
                const int cA = 4 * s + 2 * h;      // chunk if p2
                const int cB = cA + 1;             // chunk if !p2
                const int iA = CI[cA], iB = CI[cB];
                const int oA = CO[cA], oB = CO[cB];
                #pragma unroll
                for (int t2 = 0; t2 < 2; t2++) {
                    #pragma unroll
                    for (int pp = 0; pp < 2; pp++) {
                        const int p = t2 * 2 + pp;
                        __half2 xi2;
                        if (iA == iB) {
                            xi2 = dup_half(xh[p][iA >> 1], iA & 1);
                        } else {
                            __half2 dA = dup_half(xh[p][iA >> 1], iA & 1);
                            __half2 dB = dup_half(xh[p][iB >> 1], iB & 1);
                            xi2 = p2 ? dA : dB;
                        }
                        __half2 xv = (oA == oB) ? xq[p][oA]
                                                : (p2 ? xq[p][oA] : xq[p][oB]);
                        __half2 prod = __hmul2(xi2, xv);
                        a[t2][pp + 2 * h] = *(uint32_t*)&prod;
                    }
                }
            }
            #pragma unroll
            for (int n = 0; n < 4; n++) {
                uint32_t b0, b1;
                ldsv2(b0, b1, bRd + ((uint32_t)(n * 8) * BST + (uint32_t)s * 8u) * 4u);
                mma_f16(c[0][n], a[0][0], a[0][1], a[0][2], a[0][3], b0, b1);
                mma_f16(c[1][n], a[1][0], a[1][1], a[1][2], a[1][3], b0, b1);
            }
        }
        {   // linear step s = 10: fragments are xq pairs directly
            uint32_t a[2][4];
            #pragma unroll
            for (int t2 = 0; t2 < 2; t2++) {
                #pragma unroll
                for (int pp = 0; pp < 2; pp++) {
                    const int p = t2 * 2 + pp;
                    __half2 v0 = p2 ? xq[p][0] : xq[p][1];
                    __half2 v1 = p2 ? xq[p][2] : xq[p][3];
                    a[t2][pp]     = *(uint32_t*)&v0;
                    a[t2][pp + 2] = *(uint32_t*)&v1;
                }
            }
            #pragma unroll
            for (int n = 0; n < 4; n++) {
                uint32_t b0, b1;
                ldsv2(b0, b1, bRd + ((uint32_t)(n * 8) * BST + 80u) * 4u);
                mma_f16(c[0][n], a[0][0], a[0][1], a[0][2], a[0][3], b0, b1);
                mma_f16(c[1][n], a[1][0], a[1][1], a[1][2], a[1][3], b0, b1);
            }
        }

        // ---- epilogue: add per-component const, exp, logsumexp ----
        #pragma unroll
        for (int t2 = 0; t2 < 2; t2++) {
            float S0 = 0.f, S1 = 0.f;
            #pragma unroll
            for (int n = 0; n < 4; n++) {
                S0 += __expf(c[t2][n][0] + kc[n][0]) + __expf(c[t2][n][1] + kc[n][1]);
                S1 += __expf(c[t2][n][2] + kc[n][0]) + __expf(c[t2][n][3] + kc[n][1]);
            }
            S0 += __shfl_xor_sync(0xffffffffu, S0, 1);
            S0 += __shfl_xor_sync(0xffffffffu, S0, 2);
            S1 += __shfl_xor_sync(0xffffffffu, S1, 1);
            S1 += __shfl_xor_sync(0xffffffffu, S1, 2);
            if (tg == 0) {
                int r0 = base + t2 * 16 + gr;
                if (r0 < N)     acc += __logf(S0);
                if (r0 + 8 < N) acc += __logf(S1);
            }
        }
    }

    s_red[tid] = acc;
    __syncthreads();
    for (int s = TPB / 2; s > 0; s >>= 1) {
        if (tid < s) s_red[tid] += s_red[tid + s];
        __syncthreads();
    }
    if (tid == 0) g_partial[blockIdx.x] = s_red[0];
}

// ---------------------------------------------------------------------------
__global__ void mog_final(float* __restrict__ out, int N, int nBlocks)
{
    __shared__ double red[256];
    double s = 0.0;
    for (int i = threadIdx.x; i < nBlocks; i += 256) s += (double)g_partial[i];
    red[threadIdx.x] = s;
    __syncthreads();
    for (int st = 128; st > 0; st >>= 1) {
        if (threadIdx.x < st) red[threadIdx.x] += red[threadIdx.x + st];
        __syncthreads();
    }
    if (threadIdx.x == 0) out[0] = (float)(red[0] / (double)N);
}

// ---------------------------------------------------------------------------
extern "C" void kernel_launch(void* const* d_in, const int* in_sizes, int n_in,
                              void* d_out, int out_size)
{
    const float* data      = (const float*)d_in[0];
    const float* means     = (const float*)d_in[1];
    const float* cov_parts = (const float*)d_in[2];
    const float* logw      = (const float*)d_in[3];
    float* out = (float*)d_out;

    const int N = in_sizes[0] / DDIM;

    int sm = 148;
    cudaDeviceGetAttribute(&sm, cudaDevAttrMultiProcessorCount, 0);
    if (sm > 680) sm = 680;

    const int nIt = (N + TPB - 1) / TPB;
    int grid = sm * 4;
    if (grid > nIt) grid = nIt;
    if (grid > 2048) grid = 2048;

    mog_setup<<<KCOMP, 32>>>(means, cov_parts, logw);
    mog_main<<<grid, TPB>>>(data, N, nIt, grid);
    mog_final<<<1, 256>>>(out, N, grid);
}